// round 1
// baseline (speedup 1.0000x reference)
#include <cuda_runtime.h>
#include <cuda_bf16.h>

// Problem shape (fixed by dataset, derived defensively from in_sizes)
#define EDIM 512
#define TM 64        // tokens per block
#define TQ 64        // codebook chunk per iteration
#define KB 32        // k-slab staged in smem
#define NTHREADS 256

#define MAX_N 16384
#define MAX_Q 8192

// Scratch (no allocations allowed -> device globals)
__device__ float g_xsq[MAX_N];
__device__ float g_wsq[MAX_Q];

// ---------------------------------------------------------------------------
// Kernel 1: row sums of squares.
// x_sq MUST replicate the reference's rounding order: strict sequential scalar
// acc = acc + (v*v), e ascending, fp32, NO fma contraction (XLA CPU emits the
// reduction without reassociation, so it stays a sequential scalar loop).
// w_sq magnitude ~5e-4 is 6 decades below the dist ulp grid; same code reused.
// ---------------------------------------------------------------------------
__global__ void rowsq_kernel(const float* __restrict__ x,
                             const float* __restrict__ w,
                             int N, int Q) {
    int r = blockIdx.x * blockDim.x + threadIdx.x;
    if (r < N) {
        const float* p = x + (size_t)r * EDIM;
        float acc = 0.0f;
        for (int e = 0; e < EDIM; ++e) {
            float v = __ldg(p + e);
            acc = __fadd_rn(acc, __fmul_rn(v, v));   // no FMA, sequential
        }
        g_xsq[r] = acc;
    } else if (r < N + Q) {
        int q = r - N;
        const float* p = w + (size_t)q * EDIM;
        float acc = 0.0f;
        for (int e = 0; e < EDIM; ++e) {
            float v = __ldg(p + e);
            acc = __fadd_rn(acc, __fmul_rn(v, v));
        }
        g_wsq[q] = acc;
    }
}

// ---------------------------------------------------------------------------
// Kernel 2: fused dist + argmin + gather.
// Each block owns TM=64 tokens and loops over all Q codes in TQ=64 chunks.
// dot[t][q] accumulated with ONE register accumulator, k ascending, fmaf ->
// matches Eigen gebp's sequential-k FMA accumulation to ~1e-9 (<< dist ulp).
// dist replicates reference association exactly:
//     t   = round(x_sq - 2*dot)     (2*dot exact; single rounding)
//     dist= round(t + w_sq)
// Argmin: strict '<', q ascending -> first-index tie-break like jnp.argmin.
// ---------------------------------------------------------------------------
__global__ void __launch_bounds__(NTHREADS)
vq_kernel(const float* __restrict__ x,
          const float* __restrict__ w,
          float* __restrict__ out,
          int N, int Q, long long out_elems) {
    __shared__ float xs[KB][TM + 1];
    __shared__ float ws[KB][TQ + 1];
    __shared__ float dist[TM][TQ + 1];
    __shared__ float xsql[TM];
    __shared__ int   ibuf[TM];

    const int tid = threadIdx.x;
    const int t0  = blockIdx.x * TM;
    const int ty  = tid >> 4;    // 0..15 -> 4 tokens each
    const int tx  = tid & 15;    // 0..15 -> 4 codes each

    if (tid < TM) xsql[tid] = g_xsq[t0 + tid];
    __syncthreads();

    float bestv = 3.4e38f;
    int   besti = 0;

    const int c  = tid & 31;     // k within slab (coalesced global load)
    const int r0 = tid >> 5;     // 0..7

    for (int qc = 0; qc < Q; qc += TQ) {
        float acc[4][4];
        #pragma unroll
        for (int i = 0; i < 4; ++i)
            #pragma unroll
            for (int j = 0; j < 4; ++j) acc[i][j] = 0.0f;

        for (int kb = 0; kb < EDIM; kb += KB) {
            // Stage x and w slabs (transposed into [k][row], +1 pad: no conflicts)
            #pragma unroll
            for (int p = 0; p < TM; p += 8) {
                int row = r0 + p;
                xs[c][row] = x[(size_t)(t0 + row) * EDIM + kb + c];
                ws[c][row] = w[(size_t)(qc + row) * EDIM + kb + c];
            }
            __syncthreads();

            #pragma unroll 8
            for (int k = 0; k < KB; ++k) {
                float xv[4], wv[4];
                #pragma unroll
                for (int i = 0; i < 4; ++i) xv[i] = xs[k][ty * 4 + i];
                #pragma unroll
                for (int j = 0; j < 4; ++j) wv[j] = ws[k][tx * 4 + j];
                #pragma unroll
                for (int i = 0; i < 4; ++i)
                    #pragma unroll
                    for (int j = 0; j < 4; ++j)
                        acc[i][j] = __fmaf_rn(xv[i], wv[j], acc[i][j]);
            }
            __syncthreads();
        }

        // Epilogue: replicate reference rounding exactly.
        #pragma unroll
        for (int i = 0; i < 4; ++i) {
            float xq = xsql[ty * 4 + i];
            #pragma unroll
            for (int j = 0; j < 4; ++j) {
                float wq = g_wsq[qc + tx * 4 + j];
                float t  = __fsub_rn(xq, 2.0f * acc[i][j]);  // 2*acc exact
                float d  = __fadd_rn(t, wq);
                dist[ty * 4 + i][tx * 4 + j] = d;
            }
        }
        __syncthreads();

        if (tid < TM) {
            #pragma unroll 8
            for (int j = 0; j < TQ; ++j) {
                float v = dist[tid][j];
                if (v < bestv) { bestv = v; besti = qc + j; }
            }
        }
        __syncthreads();
    }

    if (tid < TM) ibuf[tid] = besti;
    __syncthreads();

    // Gather codebook rows (bitwise copy of weight rows, like weight[q_idx])
    for (int idx = tid; idx < TM * EDIM; idx += NTHREADS) {
        int t = idx >> 9;          // /512
        int e = idx & (EDIM - 1);
        out[(size_t)(t0 + t) * EDIM + e] = w[(size_t)ibuf[t] * EDIM + e];
    }

    // idx output appended after the data block (as float, per output dtype)
    long long NE = (long long)N * EDIM;
    if (out_elems >= NE + N && tid < TM) {
        out[NE + t0 + tid] = (float)ibuf[tid];
    }
}

// ---------------------------------------------------------------------------
extern "C" void kernel_launch(void* const* d_in, const int* in_sizes, int n_in,
                              void* d_out, int out_size) {
    const float* x = (const float*)d_in[0];
    const float* w = (const float*)d_in[1];
    float* out = (float*)d_out;

    int N = in_sizes[0] / EDIM;   // 16384
    int Q = in_sizes[1] / EDIM;   // 8192
    if (N > MAX_N) N = MAX_N;
    if (Q > MAX_Q) Q = MAX_Q;

    int rows = N + Q;
    rowsq_kernel<<<(rows + 255) / 256, 256>>>(x, w, N, Q);

    int nblocks = N / TM;
    vq_kernel<<<nblocks, NTHREADS>>>(x, w, out, N, Q, (long long)out_size);
}

// round 3
// speedup vs baseline: 2.1888x; 2.1888x over previous
#include <cuda_runtime.h>
#include <cuda_bf16.h>

#define EDIM 512
#define TM 128          // tokens per CTA
#define TQ 128          // codes per chunk
#define KC 64           // k per slab
#define NKC (EDIM/KC)   // 8
#define THREADS 256
#define MARGIN 0.015f
#define CAP 64
#define MAX_N 16384
#define MAX_Q 8192

// ---- device scratch (no allocations allowed) ----
__device__ float g_xsq[MAX_N];
__device__ float g_wsq[MAX_Q];
__device__ __nv_bfloat16 g_xbf[(size_t)MAX_N * EDIM];
__device__ __nv_bfloat16 g_wbf[(size_t)MAX_Q * EDIM];

// ---- smem layout (byte offsets into dynamic smem) ----
#define OF_X    0
#define X_BYTES (TM*EDIM*2)            // 131072
#define OF_W    (OF_X + X_BYTES)
#define WBUF    (TQ*KC*2)              // 16384
#define OF_WSQ  (OF_W + 2*WBUF)        // 163840
#define OF_RUN  (OF_WSQ + TQ*4)        // runmin keys (u32), 128
#define OF_NC   (OF_RUN + TM*4)        // candidate counters
#define OF_CAND (OF_NC + TM*4)         // cand[128][CAP]
#define OF_IBUF (OF_CAND + TM*CAP*4)
#define SMEM_TOTAL (OF_IBUF + TM*4)    // ~198.7 KB

// ======================= helpers =======================
__device__ __forceinline__ unsigned smem_u32(const void* p) {
    unsigned a;
    asm("{ .reg .u64 t; cvta.to.shared.u64 t, %1; cvt.u32.u64 %0, t; }"
        : "=r"(a) : "l"(p));
    return a;
}
// order-preserving float->u32 key (ascending)
__device__ __forceinline__ unsigned fkey(float f) {
    unsigned u = __float_as_uint(f);
    return (u & 0x80000000u) ? ~u : (u | 0x80000000u);
}
__device__ __forceinline__ float funkey(unsigned k) {
    unsigned u = (k & 0x80000000u) ? (k & 0x7FFFFFFFu) : ~k;
    return __uint_as_float(u);
}

#define CP_ASYNC16(dst, src) \
    asm volatile("cp.async.cg.shared.global [%0], [%1], 16;" \
                 :: "r"(dst), "l"(src) : "memory")

#define LDSM_X4(a0,a1,a2,a3,addr) \
    asm volatile("ldmatrix.sync.aligned.m8n8.x4.shared.b16 {%0,%1,%2,%3}, [%4];" \
        : "=r"(a0),"=r"(a1),"=r"(a2),"=r"(a3) : "r"(addr))
#define LDSM_X2(b0,b1,addr) \
    asm volatile("ldmatrix.sync.aligned.m8n8.x2.shared.b16 {%0,%1}, [%2];" \
        : "=r"(b0),"=r"(b1) : "r"(addr))
#define MMA16816(c, a, b) \
    asm volatile("mma.sync.aligned.m16n8k16.row.col.f32.bf16.bf16.f32 " \
        "{%0,%1,%2,%3}, {%4,%5,%6,%7}, {%8,%9}, {%0,%1,%2,%3};" \
        : "+f"((c)[0]),"+f"((c)[1]),"+f"((c)[2]),"+f"((c)[3]) \
        : "r"((a)[0]),"r"((a)[1]),"r"((a)[2]),"r"((a)[3]), \
          "r"((b)[0]),"r"((b)[1]))

// ======================= pre-kernels =======================
__global__ void convert_kernel(const float* __restrict__ x,
                               const float* __restrict__ w,
                               size_t nx, size_t nw) {
    size_t i = (size_t)blockIdx.x * blockDim.x + threadIdx.x;
    size_t stride = (size_t)gridDim.x * blockDim.x;
    for (size_t k = i; k < nx; k += stride) g_xbf[k] = __float2bfloat16(x[k]);
    for (size_t k = i; k < nw; k += stride) g_wbf[k] = __float2bfloat16(w[k]);
}

// sequential rounding order (validated bitwise in round 1)
__global__ void rowsq_kernel(const float* __restrict__ x,
                             const float* __restrict__ w, int N, int Q) {
    int r = blockIdx.x * blockDim.x + threadIdx.x;
    const float* p = 0;
    float* dst = 0;
    if (r < N) { p = x + (size_t)r * EDIM; dst = &g_xsq[r]; }
    else if (r < N + Q) { p = w + (size_t)(r - N) * EDIM; dst = &g_wsq[r - N]; }
    else return;
    const float4* p4 = (const float4*)p;
    float acc = 0.0f;
    for (int e = 0; e < EDIM / 4; ++e) {
        float4 v = __ldg(p4 + e);
        acc = __fadd_rn(acc, __fmul_rn(v.x, v.x));
        acc = __fadd_rn(acc, __fmul_rn(v.y, v.y));
        acc = __fadd_rn(acc, __fmul_rn(v.z, v.z));
        acc = __fadd_rn(acc, __fmul_rn(v.w, v.w));
    }
    *dst = acc;
}

// ======================= main kernel =======================
__global__ void __launch_bounds__(THREADS, 1)
vq_mma_kernel(const float* __restrict__ x, const float* __restrict__ w,
              float* __restrict__ out, int N, int Q, long long out_elems) {
    extern __shared__ char S[];
    const unsigned sb = smem_u32(S);

    const int tid  = threadIdx.x;
    const int lane = tid & 31;
    const int wid  = tid >> 5;
    const int wm   = wid >> 2;   // 0..1 (m)
    const int wn   = wid & 3;    // 0..3 (n)
    const int t0   = blockIdx.x * TM;

    unsigned* runk = (unsigned*)(S + OF_RUN);
    int*      ncnt = (int*)(S + OF_NC);
    int*      cand = (int*)(S + OF_CAND);
    float*    wsqs = (float*)(S + OF_WSQ);

    if (tid < TM) { runk[tid] = 0xFFFFFFFFu; ncnt[tid] = 0; }

    // resident X tile: 128 x 512 bf16, swizzled (row stride 1024B)
    const __nv_bfloat16* xb = g_xbf + (size_t)t0 * EDIM;
    for (int v = tid; v < TM * 64; v += THREADS) {
        int row = v >> 6, u = v & 63;
        uint4 val = *(const uint4*)(xb + (size_t)row * EDIM + u * 8);
        *(uint4*)(S + OF_X + row * 1024 + ((u * 16) ^ ((row & 7) << 4))) = val;
    }
    __syncthreads();

    for (int qc = 0; qc < Q; qc += TQ) {
        if (tid < TQ) wsqs[tid] = g_wsq[qc + tid];

        // prologue: stage W slab kc=0 into buf 0
        {
            const __nv_bfloat16* src = g_wbf + (size_t)qc * EDIM;
            for (int v = tid; v < TQ * 8; v += THREADS) {
                int row = v >> 3, u = v & 7;
                unsigned dst = sb + OF_W + row * 128 + ((u * 16) ^ ((row & 7) << 4));
                CP_ASYNC16(dst, src + (size_t)row * EDIM + u * 8);
            }
            asm volatile("cp.async.commit_group;" ::: "memory");
        }

        float acc[4][4][4];
        #pragma unroll
        for (int i = 0; i < 4; ++i)
            #pragma unroll
            for (int j = 0; j < 4; ++j)
                #pragma unroll
                for (int k = 0; k < 4; ++k) acc[i][j][k] = 0.0f;

        for (int kc = 0; kc < NKC; ++kc) {
            const int cb = kc & 1;
            if (kc + 1 < NKC) {
                const __nv_bfloat16* src = g_wbf + (size_t)qc * EDIM + (kc + 1) * KC;
                unsigned dbase = sb + OF_W + (cb ^ 1) * WBUF;
                for (int v = tid; v < TQ * 8; v += THREADS) {
                    int row = v >> 3, u = v & 7;
                    unsigned dst = dbase + row * 128 + ((u * 16) ^ ((row & 7) << 4));
                    CP_ASYNC16(dst, src + (size_t)row * EDIM + u * 8);
                }
                asm volatile("cp.async.commit_group;" ::: "memory");
                asm volatile("cp.async.wait_group 1;" ::: "memory");
            } else {
                asm volatile("cp.async.wait_group 0;" ::: "memory");
            }
            __syncthreads();

            const unsigned wbase = sb + OF_W + cb * WBUF;
            const int l15 = lane & 15;
            #pragma unroll
            for (int ks = 0; ks < 4; ++ks) {
                unsigned a[4][4], b[4][2];
                #pragma unroll
                for (int mt = 0; mt < 4; ++mt) {
                    int row = wm * 64 + mt * 16 + (lane & 15);
                    int u = kc * 8 + ks * 2 + (lane >> 4);
                    unsigned ad = sb + OF_X + row * 1024 + ((u * 16) ^ ((row & 7) << 4));
                    LDSM_X4(a[mt][0], a[mt][1], a[mt][2], a[mt][3], ad);
                }
                #pragma unroll
                for (int nt = 0; nt < 4; ++nt) {
                    int row = wn * 32 + nt * 8 + (l15 & 7);
                    int u = ks * 2 + (l15 >> 3);
                    unsigned bd = wbase + row * 128 + ((u * 16) ^ ((row & 7) << 4));
                    LDSM_X2(b[nt][0], b[nt][1], bd);
                }
                #pragma unroll
                for (int mt = 0; mt < 4; ++mt)
                    #pragma unroll
                    for (int nt = 0; nt < 4; ++nt)
                        MMA16816(acc[mt][nt], a[mt], b[nt]);
            }
            __syncthreads();   // all warps done with this buffer
        }

        // ---- epilogue: s = wsq - 2*dot; phase1 running-min, phase2 candidates ----
        float wsv[4][2];
        const int cbase = wn * 32 + 2 * (lane & 3);
        #pragma unroll
        for (int nt = 0; nt < 4; ++nt) {
            wsv[nt][0] = wsqs[cbase + nt * 8];
            wsv[nt][1] = wsqs[cbase + nt * 8 + 1];
        }
        #pragma unroll
        for (int mt = 0; mt < 4; ++mt) {
            float mlo = 3.4e38f, mhi = 3.4e38f;
            #pragma unroll
            for (int nt = 0; nt < 4; ++nt) {
                acc[mt][nt][0] = __fmaf_rn(-2.0f, acc[mt][nt][0], wsv[nt][0]);
                acc[mt][nt][1] = __fmaf_rn(-2.0f, acc[mt][nt][1], wsv[nt][1]);
                acc[mt][nt][2] = __fmaf_rn(-2.0f, acc[mt][nt][2], wsv[nt][0]);
                acc[mt][nt][3] = __fmaf_rn(-2.0f, acc[mt][nt][3], wsv[nt][1]);
                mlo = fminf(mlo, fminf(acc[mt][nt][0], acc[mt][nt][1]));
                mhi = fminf(mhi, fminf(acc[mt][nt][2], acc[mt][nt][3]));
            }
            int rlo = wm * 64 + mt * 16 + (lane >> 2);
            atomicMin(&runk[rlo], fkey(mlo));
            atomicMin(&runk[rlo + 8], fkey(mhi));
        }
        __syncthreads();
        #pragma unroll
        for (int mt = 0; mt < 4; ++mt) {
            int rlo = wm * 64 + mt * 16 + (lane >> 2);
            float thrlo = funkey(runk[rlo]) + MARGIN;
            float thrhi = funkey(runk[rlo + 8]) + MARGIN;
            #pragma unroll
            for (int nt = 0; nt < 4; ++nt) {
                int c0 = qc + cbase + nt * 8;
                if (acc[mt][nt][0] < thrlo) {
                    int p = atomicAdd(&ncnt[rlo], 1);
                    if (p < CAP) cand[rlo * CAP + p] = c0;
                }
                if (acc[mt][nt][1] < thrlo) {
                    int p = atomicAdd(&ncnt[rlo], 1);
                    if (p < CAP) cand[rlo * CAP + p] = c0 + 1;
                }
                if (acc[mt][nt][2] < thrhi) {
                    int p = atomicAdd(&ncnt[rlo + 8], 1);
                    if (p < CAP) cand[(rlo + 8) * CAP + p] = c0;
                }
                if (acc[mt][nt][3] < thrhi) {
                    int p = atomicAdd(&ncnt[rlo + 8], 1);
                    if (p < CAP) cand[(rlo + 8) * CAP + p] = c0 + 1;
                }
            }
        }
        __syncthreads();
    }

    // ---- exact rescore (validated reference-rounding replication) ----
    int* ibuf = (int*)(S + OF_IBUF);
    if (tid < TM) {
        const int t = t0 + tid;
        const float xsq = g_xsq[t];
        const float* xr = x + (size_t)t * EDIM;
        float bestd = 3.4e38f;
        int bestq = 0x7FFFFFFF;
        int nc = ncnt[tid];
        if (nc <= CAP) {
            for (int i = 0; i < nc; ++i) {
                int q = cand[tid * CAP + i];
                const float* wr = w + (size_t)q * EDIM;
                float dot = 0.0f;
                for (int e = 0; e < EDIM; ++e) dot = __fmaf_rn(xr[e], wr[e], dot);
                float d = __fadd_rn(__fsub_rn(xsq, 2.0f * dot), g_wsq[q]);
                if (d < bestd || (d == bestd && q < bestq)) { bestd = d; bestq = q; }
            }
        } else {   // overflow fallback: exact full scan (correctness guarantee)
            for (int q = 0; q < Q; ++q) {
                const float* wr = w + (size_t)q * EDIM;
                float dot = 0.0f;
                for (int e = 0; e < EDIM; ++e) dot = __fmaf_rn(xr[e], wr[e], dot);
                float d = __fadd_rn(__fsub_rn(xsq, 2.0f * dot), g_wsq[q]);
                if (d < bestd) { bestd = d; bestq = q; }
            }
        }
        ibuf[tid] = bestq;
    }
    __syncthreads();

    // ---- coalesced gather of codebook rows + idx tail (validated layout) ----
    const float4* w4 = (const float4*)w;
    float4* o4 = (float4*)out;
    for (int u = tid; u < TM * (EDIM / 4); u += THREADS) {
        int row = u >> 7, e4 = u & 127;
        o4[(size_t)(t0 + row) * (EDIM / 4) + e4] = w4[(size_t)ibuf[row] * (EDIM / 4) + e4];
    }
    long long NE = (long long)N * EDIM;
    if (out_elems >= NE + N && tid < TM) out[NE + t0 + tid] = (float)ibuf[tid];
}

// ======================= launch =======================
extern "C" void kernel_launch(void* const* d_in, const int* in_sizes, int n_in,
                              void* d_out, int out_size) {
    const float* x = (const float*)d_in[0];
    const float* w = (const float*)d_in[1];
    float* out = (float*)d_out;

    int N = in_sizes[0] / EDIM;   // 16384
    int Q = in_sizes[1] / EDIM;   // 8192
    if (N > MAX_N) N = MAX_N;
    if (Q > MAX_Q) Q = MAX_Q;

    cudaFuncSetAttribute(vq_mma_kernel,
                         cudaFuncAttributeMaxDynamicSharedMemorySize, SMEM_TOTAL);

    convert_kernel<<<1024, 256>>>(x, w, (size_t)N * EDIM, (size_t)Q * EDIM);
    rowsq_kernel<<<(N + Q + 255) / 256, 256>>>(x, w, N, Q);
    vq_mma_kernel<<<N / TM, THREADS, SMEM_TOTAL>>>(x, w, out, N, Q,
                                                   (long long)out_size);
}

// round 4
// speedup vs baseline: 3.6521x; 1.6686x over previous
#include <cuda_runtime.h>
#include <cuda_bf16.h>

#define EDIM 512
#define TM 128          // tokens per CTA
#define TQ 256          // codes per chunk (widened)
#define KC 64           // k per slab
#define NKC (EDIM/KC)   // 8
#define THREADS 256
#define MARGIN 0.015f
#define CAPG 64
#define MAX_N 16384
#define MAX_Q 8192
#define CONVB 512       // blocks doing conversion in prep kernel

// ---- device scratch (no allocations allowed) ----
__device__ float g_xsq[MAX_N];
__device__ float g_wsq[MAX_Q];
__device__ __nv_bfloat16 g_xbf[(size_t)MAX_N * EDIM];
__device__ __nv_bfloat16 g_wbf[(size_t)MAX_Q * EDIM];
__device__ int g_nc[MAX_N];
__device__ int g_cand[(size_t)MAX_N * CAPG];

// ---- smem layout ----
#define OF_X    0
#define X_BYTES (TM*EDIM*2)            // 131072
#define OF_W    (OF_X + X_BYTES)
#define WBUF    (TQ*KC*2)              // 32768
#define OF_WSQ  (OF_W + 2*WBUF)        // 196608
#define OF_RUN  (OF_WSQ + TQ*4)        // 197632
#define OF_IBUF (OF_RUN + TM*4)        // 198144
#define SMEM_TOTAL (OF_IBUF + TM*4)    // 198656

// ======================= helpers =======================
__device__ __forceinline__ unsigned smem_u32(const void* p) {
    unsigned a;
    asm("{ .reg .u64 t; cvta.to.shared.u64 t, %1; cvt.u32.u64 %0, t; }"
        : "=r"(a) : "l"(p));
    return a;
}
__device__ __forceinline__ unsigned fkey(float f) {
    unsigned u = __float_as_uint(f);
    return (u & 0x80000000u) ? ~u : (u | 0x80000000u);
}
__device__ __forceinline__ float funkey(unsigned k) {
    unsigned u = (k & 0x80000000u) ? (k & 0x7FFFFFFFu) : ~k;
    return __uint_as_float(u);
}
#define CP_ASYNC16(dst, src) \
    asm volatile("cp.async.cg.shared.global [%0], [%1], 16;" \
                 :: "r"(dst), "l"(src) : "memory")
#define LDSM_X4(a0,a1,a2,a3,addr) \
    asm volatile("ldmatrix.sync.aligned.m8n8.x4.shared.b16 {%0,%1,%2,%3}, [%4];" \
        : "=r"(a0),"=r"(a1),"=r"(a2),"=r"(a3) : "r"(addr))
#define MMA16816(c, a, b) \
    asm volatile("mma.sync.aligned.m16n8k16.row.col.f32.bf16.bf16.f32 " \
        "{%0,%1,%2,%3}, {%4,%5,%6,%7}, {%8,%9}, {%0,%1,%2,%3};" \
        : "+f"((c)[0]),"+f"((c)[1]),"+f"((c)[2]),"+f"((c)[3]) \
        : "r"((a)[0]),"r"((a)[1]),"r"((a)[2]),"r"((a)[3]), \
          "r"((b)[0]),"r"((b)[1]))

// ======================= prep kernel (convert + rowsq + zero counters) ====
__global__ void prep_kernel(const float* __restrict__ x,
                            const float* __restrict__ w, int N, int Q) {
    if (blockIdx.x < CONVB) {
        size_t i = (size_t)blockIdx.x * blockDim.x + threadIdx.x;
        size_t stride = (size_t)CONVB * blockDim.x;
        size_t nx = (size_t)N * EDIM, nw = (size_t)Q * EDIM;
        for (size_t k = i; k < nx; k += stride) g_xbf[k] = __float2bfloat16(x[k]);
        for (size_t k = i; k < nw; k += stride) g_wbf[k] = __float2bfloat16(w[k]);
        for (size_t k = i; k < (size_t)N; k += stride) g_nc[k] = 0;
    } else {
        int r = (blockIdx.x - CONVB) * blockDim.x + threadIdx.x;
        const float* p; float* dst;
        if (r < N) { p = x + (size_t)r * EDIM; dst = &g_xsq[r]; }
        else if (r < N + Q) { p = w + (size_t)(r - N) * EDIM; dst = &g_wsq[r - N]; }
        else return;
        const float4* p4 = (const float4*)p;
        float acc = 0.0f;   // sequential rounding order (bitwise-validated R1)
        for (int e = 0; e < EDIM / 4; ++e) {
            float4 v = __ldg(p4 + e);
            acc = __fadd_rn(acc, __fmul_rn(v.x, v.x));
            acc = __fadd_rn(acc, __fmul_rn(v.y, v.y));
            acc = __fadd_rn(acc, __fmul_rn(v.z, v.z));
            acc = __fadd_rn(acc, __fmul_rn(v.w, v.w));
        }
        *dst = acc;
    }
}

// ======================= main kernel =======================
__global__ void __launch_bounds__(THREADS, 1)
vq_mma_kernel(const float* __restrict__ x, const float* __restrict__ w,
              float* __restrict__ out, int N, int Q, long long out_elems) {
    extern __shared__ char S[];
    const unsigned sb = smem_u32(S);

    const int tid  = threadIdx.x;
    const int lane = tid & 31;
    const int wid  = tid >> 5;
    const int wm   = wid >> 2;   // 0..1  (64 tokens each)
    const int wn   = wid & 3;    // 0..3  (64 codes each)
    const int t0   = blockIdx.x * TM;

    unsigned* runk = (unsigned*)(S + OF_RUN);
    float*    wsqs = (float*)(S + OF_WSQ);

    if (tid < TM) runk[tid] = 0xFFFFFFFFu;

    // resident X tile: 128 x 512 bf16, swizzled rows (stride 1024B)
    const __nv_bfloat16* xb = g_xbf + (size_t)t0 * EDIM;
    for (int v = tid; v < TM * 64; v += THREADS) {
        int row = v >> 6, u = v & 63;
        uint4 val = *(const uint4*)(xb + (size_t)row * EDIM + u * 8);
        *(uint4*)(S + OF_X + row * 1024 + ((u * 16) ^ ((row & 7) << 4))) = val;
    }
    __syncthreads();

    for (int qc = 0; qc < Q; qc += TQ) {
        wsqs[tid] = g_wsq[qc + tid];

        // prologue: stage slab kc=0 into buf 0  (256 rows x 64 k, bf16)
        {
            const __nv_bfloat16* src = g_wbf + (size_t)qc * EDIM;
            for (int v = tid; v < TQ * 8; v += THREADS) {
                int row = v >> 3, u = v & 7;
                unsigned dst = sb + OF_W + row * 128 + ((u * 16) ^ ((row & 7) << 4));
                CP_ASYNC16(dst, src + (size_t)row * EDIM + u * 8);
            }
            asm volatile("cp.async.commit_group;" ::: "memory");
        }

        float acc[4][8][4];
        #pragma unroll
        for (int i = 0; i < 4; ++i)
            #pragma unroll
            for (int j = 0; j < 8; ++j)
                #pragma unroll
                for (int k = 0; k < 4; ++k) acc[i][j][k] = 0.0f;

        for (int kc = 0; kc < NKC; ++kc) {
            const int cb = kc & 1;
            if (kc + 1 < NKC) {
                const __nv_bfloat16* src = g_wbf + (size_t)qc * EDIM + (kc + 1) * KC;
                unsigned dbase = sb + OF_W + (cb ^ 1) * WBUF;
                for (int v = tid; v < TQ * 8; v += THREADS) {
                    int row = v >> 3, u = v & 7;
                    unsigned dst = dbase + row * 128 + ((u * 16) ^ ((row & 7) << 4));
                    CP_ASYNC16(dst, src + (size_t)row * EDIM + u * 8);
                }
                asm volatile("cp.async.commit_group;" ::: "memory");
                asm volatile("cp.async.wait_group 1;" ::: "memory");
            } else {
                asm volatile("cp.async.wait_group 0;" ::: "memory");
            }
            __syncthreads();

            const unsigned wbase = sb + OF_W + cb * WBUF;
            #pragma unroll
            for (int ks = 0; ks < 4; ++ks) {
                unsigned a[4][4], b[8][2];
                #pragma unroll
                for (int mt = 0; mt < 4; ++mt) {
                    int row = wm * 64 + mt * 16 + (lane & 15);
                    int u = kc * 8 + ks * 2 + (lane >> 4);
                    unsigned ad = sb + OF_X + row * 1024 + ((u * 16) ^ ((row & 7) << 4));
                    LDSM_X4(a[mt][0], a[mt][1], a[mt][2], a[mt][3], ad);
                }
                // B as x4: matrices (ntp*2, u0),(ntp*2, u1),(ntp*2+1, u0),(ntp*2+1, u1)
                #pragma unroll
                for (int ntp = 0; ntp < 4; ++ntp) {
                    int mat = lane >> 3;
                    int row = wn * 64 + (ntp * 2 + (mat >> 1)) * 8 + (lane & 7);
                    int u = ks * 2 + (mat & 1);
                    unsigned bd = wbase + row * 128 + ((u * 16) ^ ((row & 7) << 4));
                    LDSM_X4(b[ntp * 2][0], b[ntp * 2][1],
                            b[ntp * 2 + 1][0], b[ntp * 2 + 1][1], bd);
                }
                #pragma unroll
                for (int mt = 0; mt < 4; ++mt)
                    #pragma unroll
                    for (int nt = 0; nt < 8; ++nt)
                        MMA16816(acc[mt][nt], a[mt], b[nt]);
            }
            __syncthreads();   // all warps done with this buffer
        }

        // ---- epilogue: s = wsq - 2*dot; phase1 running-min, phase2 candidates ----
        float wsv[8][2];
        const int cbase = wn * 64 + 2 * (lane & 3);
        #pragma unroll
        for (int nt = 0; nt < 8; ++nt) {
            wsv[nt][0] = wsqs[cbase + nt * 8];
            wsv[nt][1] = wsqs[cbase + nt * 8 + 1];
        }
        #pragma unroll
        for (int mt = 0; mt < 4; ++mt) {
            float mlo = 3.4e38f, mhi = 3.4e38f;
            #pragma unroll
            for (int nt = 0; nt < 8; ++nt) {
                acc[mt][nt][0] = __fmaf_rn(-2.0f, acc[mt][nt][0], wsv[nt][0]);
                acc[mt][nt][1] = __fmaf_rn(-2.0f, acc[mt][nt][1], wsv[nt][1]);
                acc[mt][nt][2] = __fmaf_rn(-2.0f, acc[mt][nt][2], wsv[nt][0]);
                acc[mt][nt][3] = __fmaf_rn(-2.0f, acc[mt][nt][3], wsv[nt][1]);
                mlo = fminf(mlo, fminf(acc[mt][nt][0], acc[mt][nt][1]));
                mhi = fminf(mhi, fminf(acc[mt][nt][2], acc[mt][nt][3]));
            }
            int rlo = wm * 64 + mt * 16 + (lane >> 2);
            atomicMin(&runk[rlo], fkey(mlo));
            atomicMin(&runk[rlo + 8], fkey(mhi));
        }
        __syncthreads();
        #pragma unroll
        for (int mt = 0; mt < 4; ++mt) {
            int rlo = wm * 64 + mt * 16 + (lane >> 2);
            float thrlo = funkey(runk[rlo]) + MARGIN;
            float thrhi = funkey(runk[rlo + 8]) + MARGIN;
            int tlo = t0 + rlo, thi = tlo + 8;
            #pragma unroll
            for (int nt = 0; nt < 8; ++nt) {
                int c0 = qc + cbase + nt * 8;
                if (acc[mt][nt][0] < thrlo) {
                    int p = atomicAdd(&g_nc[tlo], 1);
                    if (p < CAPG) g_cand[(size_t)tlo * CAPG + p] = c0;
                }
                if (acc[mt][nt][1] < thrlo) {
                    int p = atomicAdd(&g_nc[tlo], 1);
                    if (p < CAPG) g_cand[(size_t)tlo * CAPG + p] = c0 + 1;
                }
                if (acc[mt][nt][2] < thrhi) {
                    int p = atomicAdd(&g_nc[thi], 1);
                    if (p < CAPG) g_cand[(size_t)thi * CAPG + p] = c0;
                }
                if (acc[mt][nt][3] < thrhi) {
                    int p = atomicAdd(&g_nc[thi], 1);
                    if (p < CAPG) g_cand[(size_t)thi * CAPG + p] = c0 + 1;
                }
            }
        }
        __syncthreads();
    }

    // ---- exact rescore (validated reference-rounding replication) ----
    int* ibuf = (int*)(S + OF_IBUF);
    if (tid < TM) {
        const int t = t0 + tid;
        const float xsq = g_xsq[t];
        const float* xr = x + (size_t)t * EDIM;
        float bestd = 3.4e38f;
        int bestq = 0x7FFFFFFF;
        int nc = g_nc[t];
        if (nc <= CAPG) {
            for (int i = 0; i < nc; ++i) {
                int q = g_cand[(size_t)t * CAPG + i];
                const float* wr = w + (size_t)q * EDIM;
                float dot = 0.0f;
                for (int e = 0; e < EDIM; ++e) dot = __fmaf_rn(xr[e], wr[e], dot);
                float d = __fadd_rn(__fsub_rn(xsq, 2.0f * dot), g_wsq[q]);
                if (d < bestd || (d == bestd && q < bestq)) { bestd = d; bestq = q; }
            }
        } else {   // overflow fallback: exact full scan
            for (int q = 0; q < Q; ++q) {
                const float* wr = w + (size_t)q * EDIM;
                float dot = 0.0f;
                for (int e = 0; e < EDIM; ++e) dot = __fmaf_rn(xr[e], wr[e], dot);
                float d = __fadd_rn(__fsub_rn(xsq, 2.0f * dot), g_wsq[q]);
                if (d < bestd) { bestd = d; bestq = q; }
            }
        }
        ibuf[tid] = bestq;
    }
    __syncthreads();

    // ---- coalesced gather of codebook rows + idx tail ----
    const float4* w4 = (const float4*)w;
    float4* o4 = (float4*)out;
    for (int u = tid; u < TM * (EDIM / 4); u += THREADS) {
        int row = u >> 7, e4 = u & 127;
        o4[(size_t)(t0 + row) * (EDIM / 4) + e4] = w4[(size_t)ibuf[row] * (EDIM / 4) + e4];
    }
    long long NE = (long long)N * EDIM;
    if (out_elems >= NE + N && tid < TM) out[NE + t0 + tid] = (float)ibuf[tid];
}

// ======================= launch =======================
extern "C" void kernel_launch(void* const* d_in, const int* in_sizes, int n_in,
                              void* d_out, int out_size) {
    const float* x = (const float*)d_in[0];
    const float* w = (const float*)d_in[1];
    float* out = (float*)d_out;

    int N = in_sizes[0] / EDIM;   // 16384
    int Q = in_sizes[1] / EDIM;   // 8192
    if (N > MAX_N) N = MAX_N;
    if (Q > MAX_Q) Q = MAX_Q;

    cudaFuncSetAttribute(vq_mma_kernel,
                         cudaFuncAttributeMaxDynamicSharedMemorySize, SMEM_TOTAL);

    int rowblocks = (N + Q + THREADS - 1) / THREADS;
    prep_kernel<<<CONVB + rowblocks, THREADS>>>(x, w, N, Q);
    vq_mma_kernel<<<N / TM, THREADS, SMEM_TOTAL>>>(x, w, out, N, Q,
                                                   (long long)out_size);
}

// round 5
// speedup vs baseline: 3.8195x; 1.0459x over previous
#include <cuda_runtime.h>
#include <cuda_bf16.h>

#define EDIM 512
#define TM 128          // tokens per CTA
#define TQ 256          // codes per chunk
#define KC 64           // k per slab
#define NKC (EDIM/KC)   // 8
#define THREADS 512
#define MARGIN 0.015f
#define CAPG 64
#define MAX_N 16384
#define MAX_Q 8192
#define CONVB 512

// ---- device scratch (no allocations allowed) ----
__device__ float g_xsq[MAX_N];
__device__ float g_wsq[MAX_Q];
__device__ __nv_bfloat16 g_xbf[(size_t)MAX_N * EDIM];
__device__ __nv_bfloat16 g_wbf[(size_t)MAX_Q * EDIM];
__device__ int g_nc[MAX_N];
__device__ int g_cand[(size_t)MAX_N * CAPG];

// ---- smem layout ----
#define OF_X    0
#define X_BYTES (TM*EDIM*2)            // 131072
#define OF_W    (OF_X + X_BYTES)
#define WBUF    (TQ*KC*2)              // 32768
#define OF_WSQ  (OF_W + 2*WBUF)        // 196608
#define OF_RUN  (OF_WSQ + TQ*4)        // 197632
#define OF_IBUF (OF_RUN + TM*4)        // 198144
#define SMEM_TOTAL (OF_IBUF + TM*4)    // 198656

// ======================= helpers =======================
__device__ __forceinline__ unsigned smem_u32(const void* p) {
    unsigned a;
    asm("{ .reg .u64 t; cvta.to.shared.u64 t, %1; cvt.u32.u64 %0, t; }"
        : "=r"(a) : "l"(p));
    return a;
}
__device__ __forceinline__ unsigned fkey(float f) {
    unsigned u = __float_as_uint(f);
    return (u & 0x80000000u) ? ~u : (u | 0x80000000u);
}
__device__ __forceinline__ float funkey(unsigned k) {
    unsigned u = (k & 0x80000000u) ? (k & 0x7FFFFFFFu) : ~k;
    return __uint_as_float(u);
}
#define CP_ASYNC16(dst, src) \
    asm volatile("cp.async.cg.shared.global [%0], [%1], 16;" \
                 :: "r"(dst), "l"(src) : "memory")
#define LDSM_X4(a0,a1,a2,a3,addr) \
    asm volatile("ldmatrix.sync.aligned.m8n8.x4.shared.b16 {%0,%1,%2,%3}, [%4];" \
        : "=r"(a0),"=r"(a1),"=r"(a2),"=r"(a3) : "r"(addr))
#define MMA16816(c, a, b) \
    asm volatile("mma.sync.aligned.m16n8k16.row.col.f32.bf16.bf16.f32 " \
        "{%0,%1,%2,%3}, {%4,%5,%6,%7}, {%8,%9}, {%0,%1,%2,%3};" \
        : "+f"((c)[0]),"+f"((c)[1]),"+f"((c)[2]),"+f"((c)[3]) \
        : "r"((a)[0]),"r"((a)[1]),"r"((a)[2]),"r"((a)[3]), \
          "r"((b)[0]),"r"((b)[1]))

// ======================= prep kernel =======================
__global__ void prep_kernel(const float* __restrict__ x,
                            const float* __restrict__ w, int N, int Q) {
    if (blockIdx.x < CONVB) {
        size_t i = (size_t)blockIdx.x * blockDim.x + threadIdx.x;
        size_t stride = (size_t)CONVB * blockDim.x;
        size_t nx = (size_t)N * EDIM, nw = (size_t)Q * EDIM;
        for (size_t k = i; k < nx; k += stride) g_xbf[k] = __float2bfloat16(x[k]);
        for (size_t k = i; k < nw; k += stride) g_wbf[k] = __float2bfloat16(w[k]);
        for (size_t k = i; k < (size_t)N; k += stride) g_nc[k] = 0;
    } else {
        int r = (blockIdx.x - CONVB) * blockDim.x + threadIdx.x;
        const float* p; float* dst;
        if (r < N) { p = x + (size_t)r * EDIM; dst = &g_xsq[r]; }
        else if (r < N + Q) { p = w + (size_t)(r - N) * EDIM; dst = &g_wsq[r - N]; }
        else return;
        const float4* p4 = (const float4*)p;
        float acc = 0.0f;   // sequential rounding order (bitwise-validated R1)
        for (int e = 0; e < EDIM / 4; ++e) {
            float4 v = __ldg(p4 + e);
            acc = __fadd_rn(acc, __fmul_rn(v.x, v.x));
            acc = __fadd_rn(acc, __fmul_rn(v.y, v.y));
            acc = __fadd_rn(acc, __fmul_rn(v.z, v.z));
            acc = __fadd_rn(acc, __fmul_rn(v.w, v.w));
        }
        *dst = acc;
    }
}

// ======================= main kernel =======================
// 16 warps: 4m x 4n grid; warp tile 32 tokens x 64 codes (mt=2, nt=8)
__global__ void __launch_bounds__(THREADS, 1)
vq_mma_kernel(const float* __restrict__ x, const float* __restrict__ w,
              float* __restrict__ out, int N, int Q, long long out_elems) {
    extern __shared__ char S[];
    const unsigned sb = smem_u32(S);

    const int tid  = threadIdx.x;
    const int lane = tid & 31;
    const int wid  = tid >> 5;
    const int wm   = wid >> 2;   // 0..3  (32 tokens each)
    const int wn   = wid & 3;    // 0..3  (64 codes each)
    const int t0   = blockIdx.x * TM;

    unsigned* runk = (unsigned*)(S + OF_RUN);
    float*    wsqs = (float*)(S + OF_WSQ);

    if (tid < TM) runk[tid] = 0xFFFFFFFFu;

    // resident X tile: 128 x 512 bf16, swizzled rows (stride 1024B)
    const __nv_bfloat16* xb = g_xbf + (size_t)t0 * EDIM;
    for (int v = tid; v < TM * 64; v += THREADS) {
        int row = v >> 6, u = v & 63;
        uint4 val = *(const uint4*)(xb + (size_t)row * EDIM + u * 8);
        *(uint4*)(S + OF_X + row * 1024 + ((u * 16) ^ ((row & 7) << 4))) = val;
    }
    __syncthreads();

    for (int qc = 0; qc < Q; qc += TQ) {
        if (tid < TQ) wsqs[tid] = g_wsq[qc + tid];

        // prologue: stage slab kc=0 into buf 0 (256 rows x 64 k bf16)
        {
            const __nv_bfloat16* src = g_wbf + (size_t)qc * EDIM;
            for (int v = tid; v < TQ * 8; v += THREADS) {
                int row = v >> 3, u = v & 7;
                unsigned dst = sb + OF_W + row * 128 + ((u * 16) ^ ((row & 7) << 4));
                CP_ASYNC16(dst, src + (size_t)row * EDIM + u * 8);
            }
            asm volatile("cp.async.commit_group;" ::: "memory");
        }

        float acc[2][8][4];
        #pragma unroll
        for (int i = 0; i < 2; ++i)
            #pragma unroll
            for (int j = 0; j < 8; ++j)
                #pragma unroll
                for (int k = 0; k < 4; ++k) acc[i][j][k] = 0.0f;

        for (int kc = 0; kc < NKC; ++kc) {
            const int cb = kc & 1;
            if (kc + 1 < NKC) {
                const __nv_bfloat16* src = g_wbf + (size_t)qc * EDIM + (kc + 1) * KC;
                unsigned dbase = sb + OF_W + (cb ^ 1) * WBUF;
                for (int v = tid; v < TQ * 8; v += THREADS) {
                    int row = v >> 3, u = v & 7;
                    unsigned dst = dbase + row * 128 + ((u * 16) ^ ((row & 7) << 4));
                    CP_ASYNC16(dst, src + (size_t)row * EDIM + u * 8);
                }
                asm volatile("cp.async.commit_group;" ::: "memory");
                asm volatile("cp.async.wait_group 1;" ::: "memory");
            } else {
                asm volatile("cp.async.wait_group 0;" ::: "memory");
            }
            __syncthreads();

            const unsigned wbase = sb + OF_W + cb * WBUF;
            #pragma unroll
            for (int ks = 0; ks < 4; ++ks) {
                unsigned a[2][4], b[8][2];
                #pragma unroll
                for (int mt = 0; mt < 2; ++mt) {
                    int row = wm * 32 + mt * 16 + (lane & 15);
                    int u = kc * 8 + ks * 2 + (lane >> 4);
                    unsigned ad = sb + OF_X + row * 1024 + ((u * 16) ^ ((row & 7) << 4));
                    LDSM_X4(a[mt][0], a[mt][1], a[mt][2], a[mt][3], ad);
                }
                #pragma unroll
                for (int ntp = 0; ntp < 4; ++ntp) {
                    int mat = lane >> 3;
                    int row = wn * 64 + (ntp * 2 + (mat >> 1)) * 8 + (lane & 7);
                    int u = ks * 2 + (mat & 1);
                    unsigned bd = wbase + row * 128 + ((u * 16) ^ ((row & 7) << 4));
                    LDSM_X4(b[ntp * 2][0], b[ntp * 2][1],
                            b[ntp * 2 + 1][0], b[ntp * 2 + 1][1], bd);
                }
                #pragma unroll
                for (int mt = 0; mt < 2; ++mt)
                    #pragma unroll
                    for (int nt = 0; nt < 8; ++nt)
                        MMA16816(acc[mt][nt], a[mt], b[nt]);
            }
            __syncthreads();
        }

        // ---- epilogue: s = wsq - 2*dot; phase1 running-min, phase2 candidates ----
        float wsv[8][2];
        const int cbase = wn * 64 + 2 * (lane & 3);
        #pragma unroll
        for (int nt = 0; nt < 8; ++nt) {
            wsv[nt][0] = wsqs[cbase + nt * 8];
            wsv[nt][1] = wsqs[cbase + nt * 8 + 1];
        }
        #pragma unroll
        for (int mt = 0; mt < 2; ++mt) {
            float mlo = 3.4e38f, mhi = 3.4e38f;
            #pragma unroll
            for (int nt = 0; nt < 8; ++nt) {
                acc[mt][nt][0] = __fmaf_rn(-2.0f, acc[mt][nt][0], wsv[nt][0]);
                acc[mt][nt][1] = __fmaf_rn(-2.0f, acc[mt][nt][1], wsv[nt][1]);
                acc[mt][nt][2] = __fmaf_rn(-2.0f, acc[mt][nt][2], wsv[nt][0]);
                acc[mt][nt][3] = __fmaf_rn(-2.0f, acc[mt][nt][3], wsv[nt][1]);
                mlo = fminf(mlo, fminf(acc[mt][nt][0], acc[mt][nt][1]));
                mhi = fminf(mhi, fminf(acc[mt][nt][2], acc[mt][nt][3]));
            }
            int rlo = wm * 32 + mt * 16 + (lane >> 2);
            atomicMin(&runk[rlo], fkey(mlo));
            atomicMin(&runk[rlo + 8], fkey(mhi));
        }
        __syncthreads();
        #pragma unroll
        for (int mt = 0; mt < 2; ++mt) {
            int rlo = wm * 32 + mt * 16 + (lane >> 2);
            float thrlo = funkey(runk[rlo]) + MARGIN;
            float thrhi = funkey(runk[rlo + 8]) + MARGIN;
            int tlo = t0 + rlo, thi = tlo + 8;
            #pragma unroll
            for (int nt = 0; nt < 8; ++nt) {
                int c0 = qc + cbase + nt * 8;
                if (acc[mt][nt][0] < thrlo) {
                    int p = atomicAdd(&g_nc[tlo], 1);
                    if (p < CAPG) g_cand[(size_t)tlo * CAPG + p] = c0;
                }
                if (acc[mt][nt][1] < thrlo) {
                    int p = atomicAdd(&g_nc[tlo], 1);
                    if (p < CAPG) g_cand[(size_t)tlo * CAPG + p] = c0 + 1;
                }
                if (acc[mt][nt][2] < thrhi) {
                    int p = atomicAdd(&g_nc[thi], 1);
                    if (p < CAPG) g_cand[(size_t)thi * CAPG + p] = c0;
                }
                if (acc[mt][nt][3] < thrhi) {
                    int p = atomicAdd(&g_nc[thi], 1);
                    if (p < CAPG) g_cand[(size_t)thi * CAPG + p] = c0 + 1;
                }
            }
        }
        __syncthreads();
    }

    // ---- exact rescore (validated reference-rounding replication) ----
    int* ibuf = (int*)(S + OF_IBUF);
    if (tid < TM) {
        const int t = t0 + tid;
        const float xsq = g_xsq[t];
        const float* xr = x + (size_t)t * EDIM;
        float bestd = 3.4e38f;
        int bestq = 0x7FFFFFFF;
        int nc = g_nc[t];
        if (nc <= CAPG) {
            for (int i = 0; i < nc; ++i) {
                int q = g_cand[(size_t)t * CAPG + i];
                const float* wr = w + (size_t)q * EDIM;
                float dot = 0.0f;
                for (int e = 0; e < EDIM; ++e) dot = __fmaf_rn(xr[e], wr[e], dot);
                float d = __fadd_rn(__fsub_rn(xsq, 2.0f * dot), g_wsq[q]);
                if (d < bestd || (d == bestd && q < bestq)) { bestd = d; bestq = q; }
            }
        } else {   // overflow fallback: exact full scan
            for (int q = 0; q < Q; ++q) {
                const float* wr = w + (size_t)q * EDIM;
                float dot = 0.0f;
                for (int e = 0; e < EDIM; ++e) dot = __fmaf_rn(xr[e], wr[e], dot);
                float d = __fadd_rn(__fsub_rn(xsq, 2.0f * dot), g_wsq[q]);
                if (d < bestd) { bestd = d; bestq = q; }
            }
        }
        ibuf[tid] = bestq;
    }
    __syncthreads();

    // ---- coalesced gather of codebook rows + idx tail ----
    const float4* w4 = (const float4*)w;
    float4* o4 = (float4*)out;
    for (int u = tid; u < TM * (EDIM / 4); u += THREADS) {
        int row = u >> 7, e4 = u & 127;
        o4[(size_t)(t0 + row) * (EDIM / 4) + e4] = w4[(size_t)ibuf[row] * (EDIM / 4) + e4];
    }
    long long NE = (long long)N * EDIM;
    if (out_elems >= NE + N && tid < TM) out[NE + t0 + tid] = (float)ibuf[tid];
}

// ======================= launch =======================
extern "C" void kernel_launch(void* const* d_in, const int* in_sizes, int n_in,
                              void* d_out, int out_size) {
    const float* x = (const float*)d_in[0];
    const float* w = (const float*)d_in[1];
    float* out = (float*)d_out;

    int N = in_sizes[0] / EDIM;   // 16384
    int Q = in_sizes[1] / EDIM;   // 8192
    if (N > MAX_N) N = MAX_N;
    if (Q > MAX_Q) Q = MAX_Q;

    cudaFuncSetAttribute(vq_mma_kernel,
                         cudaFuncAttributeMaxDynamicSharedMemorySize, SMEM_TOTAL);

    int rowblocks = (N + Q + 255) / 256;
    prep_kernel<<<CONVB + rowblocks, 256>>>(x, w, N, Q);
    vq_mma_kernel<<<N / TM, THREADS, SMEM_TOTAL>>>(x, w, out, N, Q,
                                                   (long long)out_size);
}